// round 5
// baseline (speedup 1.0000x reference)
#include <cuda_runtime.h>

#define EMB 100
#define BOT 5
#define NT  1024
#define FULLMASK 0xffffffffu

// One CTA per document row.
// Smem layout (dynamic, 16B-aligned sections):
//   uint32 hist[histPad]   packed 16-bit token counts (counts <= S=2048 < 65536)
//   float  stage[32*128]   per-warp (offset,coef) pairs: 64 pairs * 8B per warp
//   float  partial[32*EMB] per-warp doc partials (deterministic reduction)
//   float  zp[32]          per-warp Z partials
//   float  doc[EMB]
//   float  hv[8]           bottleneck activations (BOT=5, padded)
__global__ void __launch_bounds__(NT, 1)
doc_model_kernel(const int* __restrict__ x,
                 const float* __restrict__ we,
                 const float* __restrict__ idf,
                 const float* __restrict__ fc1w,
                 const float* __restrict__ fc1b,
                 const float* __restrict__ fc2w,
                 const float* __restrict__ fc2b,
                 float* __restrict__ out,
                 int S, int V)
{
    extern __shared__ unsigned int smem[];
    const int histPad = ((((V + 1) >> 1) + 3) & ~3);   // uint32 words, 16B multiple
    unsigned int* hist = smem;                          // histPad words
    float* stage   = (float*)(hist + histPad);          // 32 warps * 128 floats
    float* partial = stage + 32 * 128;                  // 32*EMB
    float* zp      = partial + 32 * EMB;                // 32
    float* doc     = zp + 32;                           // EMB
    float* hv      = doc + EMB;                         // 8

    const int b    = blockIdx.x;
    const int tid  = threadIdx.x;
    const int warp = tid >> 5;
    const int lane = tid & 31;

    // ---- issue token load FIRST (1 x LDG.64); its latency hides behind zeroing.
    // Warp w owns tokens [64w, 64w+64); lane l holds tokens 64w+2l, 64w+2l+1.
    const int* xr = x + (long long)b * S;
    const int2 tt = *(const int2*)(xr + (warp << 6) + (lane << 1));

    // ---- zero histogram (vectorized) ----
    uint4* h4 = (uint4*)hist;
    const int h4n = histPad >> 2;
    const uint4 z4 = make_uint4(0u, 0u, 0u, 0u);
    for (int i = tid; i < h4n; i += NT) h4[i] = z4;

    // idf gathers are independent of the histogram: issue before the barrier
    const float idf0 = __ldg(&idf[tt.x]);
    const float idf1 = __ldg(&idf[tt.y]);
    __syncthreads();

    // ---- phase 1: histogram + Z ----
    atomicAdd(&hist[tt.x >> 1], 1u << ((tt.x & 1) << 4));
    atomicAdd(&hist[tt.y >> 1], 1u << ((tt.y & 1) << 4));

    float zpart = idf0 + idf1;
    #pragma unroll
    for (int o = 16; o; o >>= 1) zpart += __shfl_xor_sync(FULLMASK, zpart, o);
    if (lane == 0) zp[warp] = zpart;
    __syncthreads();   // also orders all histogram atomics

    float z = 0.f;
    #pragma unroll
    for (int i = 0; i < 32; i++) z += zp[i];
    const float invZ = 1.0f / z;

    // ---- coefficients + staging: lane l writes its 2 (offset,coef) pairs to
    // the warp's smem strip at slots 2l, 2l+1 (one STS.128). Gather loop reads
    // slot pair k via ONE broadcast LDS.128 -- no shfls on the address path.
    const float c0 = (float)((hist[tt.x >> 1] >> ((tt.x & 1) << 4)) & 0xFFFFu)
                     * idf0 * invZ;
    const float c1 = (float)((hist[tt.y >> 1] >> ((tt.y & 1) << 4)) & 0xFFFFu)
                     * idf1 * invZ;
    float4* stW = (float4*)(stage + (warp << 7));
    stW[lane] = make_float4(__int_as_float(tt.x * (EMB * 4)), c0,
                            __int_as_float(tt.y * (EMB * 4)), c1);
    __syncwarp();

    // ---- phase 2: doc += coef * emb[t], 2 independent LDG.128 per iteration
    const bool active = lane < (EMB / 4);   // 25 lanes carry the embedding row
    const int  eoff   = lane << 4;          // byte offset within row
    const char* web = (const char*)we;
    float4 acc0 = make_float4(0.f, 0.f, 0.f, 0.f);
    float4 acc1 = make_float4(0.f, 0.f, 0.f, 0.f);

    #pragma unroll 8
    for (int k = 0; k < 32; k++) {
        const float4 q = stW[k];             // broadcast: o1,c1,o2,c2
        if (active) {
            const float4 e1 = *(const float4*)(web + __float_as_int(q.x) + eoff);
            const float4 e2 = *(const float4*)(web + __float_as_int(q.z) + eoff);
            acc0.x += q.y * e1.x; acc0.y += q.y * e1.y;
            acc0.z += q.y * e1.z; acc0.w += q.y * e1.w;
            acc1.x += q.w * e2.x; acc1.y += q.w * e2.y;
            acc1.z += q.w * e2.z; acc1.w += q.w * e2.w;
        }
    }

    if (active) {
        acc0.x += acc1.x; acc0.y += acc1.y;
        acc0.z += acc1.z; acc0.w += acc1.w;
        // partial row is 100 floats = 25 float4, rows 400B apart (16B multiple)
        ((float4*)(partial + warp * EMB))[lane] = acc0;
    }
    __syncthreads();

    // deterministic cross-warp reduction
    if (tid < EMB) {
        float d = 0.f;
        #pragma unroll
        for (int w = 0; w < 32; w++) d += partial[w * EMB + tid];
        doc[tid] = d;
    }
    __syncthreads();

    // ---- phase 3: tiny MLP 100 -> 5 -> 100 ----
    if (tid < BOT) {
        float h = __ldg(&fc1b[tid]);
        #pragma unroll
        for (int e = 0; e < EMB; e++) h += doc[e] * __ldg(&fc1w[tid * EMB + e]);
        hv[tid] = h;
    }
    __syncthreads();
    if (tid < EMB) {
        float o = __ldg(&fc2b[tid]);
        #pragma unroll
        for (int j = 0; j < BOT; j++) o += hv[j] * __ldg(&fc2w[tid * BOT + j]);
        out[(long long)b * EMB + tid] = o;
    }
}

extern "C" void kernel_launch(void* const* d_in, const int* in_sizes, int n_in,
                              void* d_out, int out_size)
{
    const int*   x    = (const int*)  d_in[0];   // [B,S] int32 token ids
    const float* we   = (const float*)d_in[1];   // [V,EMB]
    const float* idf  = (const float*)d_in[2];   // [V]
    const float* fc1w = (const float*)d_in[3];   // [BOT,EMB]
    const float* fc1b = (const float*)d_in[4];   // [BOT]
    const float* fc2w = (const float*)d_in[5];   // [EMB,BOT]
    const float* fc2b = (const float*)d_in[6];   // [EMB]
    float* out = (float*)d_out;                  // [B,EMB]

    const int V = in_sizes[2];
    const int B = out_size / EMB;
    const int S = in_sizes[0] / B;

    const int histPad = ((((V + 1) >> 1) + 3) & ~3);
    size_t smem_bytes = (size_t)histPad * 4
                      + (size_t)(32 * 128 + 32 * EMB + 32 + EMB + 8) * 4;

    cudaFuncSetAttribute(doc_model_kernel,
                         cudaFuncAttributeMaxDynamicSharedMemorySize,
                         (int)smem_bytes);

    doc_model_kernel<<<B, NT, smem_bytes>>>(x, we, idf, fc1w, fc1b, fc2w, fc2b,
                                            out, S, V);
}